// round 1
// baseline (speedup 1.0000x reference)
#include <cuda_runtime.h>
#include <cuda_bf16.h>

// Problem constants (fixed by reference setup_inputs)
#define BATCH 64
#define LC    2048
#define LA    512
#define DDIM  400

// Scratch for the rank-1 bias terms (no cudaMalloc allowed)
__device__ float g_ctxw1[BATCH * LC];   // ctx @ w1  : [64, 2048]
__device__ float g_aspw2[BATCH * LA];   // asp @ w2  : [64, 512]

// ---------------------------------------------------------------------------
// Kernel 1: row-dot  out[row] = dot(x[row, 0:400], w[0:400])
// one warp per row, float4 loads, shuffle reduce
// ---------------------------------------------------------------------------
__global__ void rowdot_kernel(const float* __restrict__ x,
                              const float* __restrict__ w,
                              float* __restrict__ out, int nrows)
{
    int warp = (blockIdx.x * (blockDim.x >> 5)) + (threadIdx.x >> 5);
    if (warp >= nrows) return;
    int lane = threadIdx.x & 31;

    const float4* xr = reinterpret_cast<const float4*>(x + (long)warp * DDIM);
    const float4* wr = reinterpret_cast<const float4*>(w);

    float s = 0.f;
    #pragma unroll 4
    for (int i = lane; i < DDIM / 4; i += 32) {
        float4 v = xr[i];
        float4 ww = wr[i];
        s += v.x * ww.x + v.y * ww.y + v.z * ww.z + v.w * ww.w;
    }
    #pragma unroll
    for (int o = 16; o > 0; o >>= 1) s += __shfl_xor_sync(0xffffffffu, s, o);
    if (lane == 0) out[warp] = s;
}

// ---------------------------------------------------------------------------
// Kernel 2: batched GEMM with fused scale + bias epilogue
//   out[b,i,j] = sum_d ctx[b,i,d]*w3[d]*asp[b,j,d] + ctxw1[b,i] + aspw2[b,j]
// Tiles: BM=128, BN=64, BK=16; 256 threads; 8x4 micro-tile per thread.
// ---------------------------------------------------------------------------
#define BM 128
#define BN 64
#define BK 16
#define TM 8
#define TN 4

__global__ __launch_bounds__(256, 4)
void gemm_bias_kernel(const float* __restrict__ ctx,
                      const float* __restrict__ asp,
                      const float* __restrict__ w3,
                      const float* __restrict__ ctxw1,
                      const float* __restrict__ aspw2,
                      float* __restrict__ out)
{
    const int b  = blockIdx.z;
    const int m0 = blockIdx.y * BM;
    const int n0 = blockIdx.x * BN;

    __shared__ float As[BK][BM];
    __shared__ float Bs[BK][BN];
    __shared__ float w3s[DDIM];

    const int tid = threadIdx.x;

    // stage w3 into smem (100 float4)
    for (int i = tid; i < DDIM / 4; i += 256)
        reinterpret_cast<float4*>(w3s)[i] = reinterpret_cast<const float4*>(w3)[i];

    const float* A  = ctx + ((long)b * LC + m0) * DDIM;
    const float* Bp = asp + ((long)b * LA + n0) * DDIM;

    const int ldRow = tid >> 2;        // 0..63
    const int ldCol = (tid & 3) * 4;   // 0,4,8,12

    const int tx = tid & 15;           // N direction (4 cols each)
    const int ty = tid >> 4;           // M direction (8 rows each)

    float acc[TM][TN];
    #pragma unroll
    for (int i = 0; i < TM; i++)
        #pragma unroll
        for (int j = 0; j < TN; j++) acc[i][j] = 0.f;

    __syncthreads();   // w3s ready

    for (int k0 = 0; k0 < DDIM; k0 += BK) {
        // ---- load A tile (128 x 16), fold w3, store transposed ----
        #pragma unroll
        for (int r = 0; r < 2; r++) {
            float4 v = *reinterpret_cast<const float4*>(
                A + (long)(ldRow + r * 64) * DDIM + k0 + ldCol);
            As[ldCol + 0][ldRow + r * 64] = v.x * w3s[k0 + ldCol + 0];
            As[ldCol + 1][ldRow + r * 64] = v.y * w3s[k0 + ldCol + 1];
            As[ldCol + 2][ldRow + r * 64] = v.z * w3s[k0 + ldCol + 2];
            As[ldCol + 3][ldRow + r * 64] = v.w * w3s[k0 + ldCol + 3];
        }
        // ---- load B tile (64 x 16), store transposed ----
        {
            float4 v = *reinterpret_cast<const float4*>(
                Bp + (long)ldRow * DDIM + k0 + ldCol);
            Bs[ldCol + 0][ldRow] = v.x;
            Bs[ldCol + 1][ldRow] = v.y;
            Bs[ldCol + 2][ldRow] = v.z;
            Bs[ldCol + 3][ldRow] = v.w;
        }
        __syncthreads();

        // ---- compute ----
        #pragma unroll
        for (int k = 0; k < BK; k++) {
            float a[TM], bb[TN];
            *reinterpret_cast<float4*>(a)     = *reinterpret_cast<const float4*>(&As[k][ty * TM]);
            *reinterpret_cast<float4*>(a + 4) = *reinterpret_cast<const float4*>(&As[k][ty * TM + 4]);
            *reinterpret_cast<float4*>(bb)    = *reinterpret_cast<const float4*>(&Bs[k][tx * TN]);
            #pragma unroll
            for (int i = 0; i < TM; i++)
                #pragma unroll
                for (int j = 0; j < TN; j++)
                    acc[i][j] += a[i] * bb[j];
        }
        __syncthreads();
    }

    // ---- epilogue: add bias terms, vectorized store ----
    float4 aw = *reinterpret_cast<const float4*>(aspw2 + b * LA + n0 + tx * TN);
    float* outb = out + ((long)b * LC + m0) * LA + n0;

    #pragma unroll
    for (int i = 0; i < TM; i++) {
        int row = ty * TM + i;
        float ct = ctxw1[b * LC + m0 + row];
        float4 o;
        o.x = acc[i][0] + ct + aw.x;
        o.y = acc[i][1] + ct + aw.y;
        o.z = acc[i][2] + ct + aw.z;
        o.w = acc[i][3] + ct + aw.w;
        *reinterpret_cast<float4*>(outb + (long)row * LA + tx * TN) = o;
    }
}

// ---------------------------------------------------------------------------
extern "C" void kernel_launch(void* const* d_in, const int* in_sizes, int n_in,
                              void* d_out, int out_size)
{
    // Identify inputs by element count (metadata order: batch_size, ctx, asp, w_u)
    const float* ctx = nullptr;
    const float* asp = nullptr;
    const float* wu  = nullptr;
    for (int i = 0; i < n_in; i++) {
        if (in_sizes[i] == BATCH * LC * DDIM)      ctx = (const float*)d_in[i];
        else if (in_sizes[i] == BATCH * LA * DDIM) asp = (const float*)d_in[i];
        else if (in_sizes[i] == 3 * DDIM)          wu  = (const float*)d_in[i];
    }

    float* out = (float*)d_out;

    float* ctxw1p = nullptr;
    float* aspw2p = nullptr;
    cudaGetSymbolAddress((void**)&ctxw1p, g_ctxw1);
    cudaGetSymbolAddress((void**)&aspw2p, g_aspw2);

    const float* w1 = wu;            // [0,400)
    const float* w2 = wu + DDIM;     // [400,800)
    const float* w3 = wu + 2 * DDIM; // [800,1200)

    // Bias term dots: one warp per row, 8 warps per block
    {
        int nrows = BATCH * LC;                  // 131072
        rowdot_kernel<<<nrows / 8, 256>>>(ctx, w1, ctxw1p, nrows);
    }
    {
        int nrows = BATCH * LA;                  // 32768
        rowdot_kernel<<<nrows / 8, 256>>>(asp, w2, aspw2p, nrows);
    }

    // Batched GEMM + fused epilogue
    dim3 grid(LA / BN, LC / BM, BATCH);          // (8, 16, 64)
    gemm_bias_kernel<<<grid, 256>>>(ctx, asp, w3, ctxw1p, aspw2p, out);
}

// round 7
// speedup vs baseline: 2.1031x; 2.1031x over previous
#include <cuda_runtime.h>
#include <cuda_bf16.h>
#include <cstdint>

// ---------------------------------------------------------------------------
// Problem constants
// ---------------------------------------------------------------------------
#define BATCH 64
#define LC    2048
#define LA    512
#define DDIM  400
#define SEG   416           // padded segment (400 data + 16 zeros)
#define KPAD  832           // [hi(400) pad16 | lo(400) pad16]
#define NKT   13            // 416 / 32 k-tiles per term
#define NSTEP 39            // 3 terms x 13 k-tiles

// GEMM tile
#define BM 256
#define BN 128
#define BKT 32

// ---------------------------------------------------------------------------
// Device scratch (no cudaMalloc allowed)
// ---------------------------------------------------------------------------
__device__ __align__(256) __nv_bfloat16 g_ctx_c[(size_t)BATCH * LC * KPAD]; // 218 MB
__device__ __align__(256) __nv_bfloat16 g_asp_c[(size_t)BATCH * LA * KPAD]; //  54 MB
__device__ float g_ctxw1[BATCH * LC];
__device__ float g_aspw2[BATCH * LA];

// ---------------------------------------------------------------------------
// Helpers
// ---------------------------------------------------------------------------
__device__ __forceinline__ uint32_t smem_to_u32(const void* p) {
    uint32_t a;
    asm("{ .reg .u64 t; cvta.to.shared.u64 t, %1; cvt.u32.u64 %0, t; }" : "=r"(a) : "l"(p));
    return a;
}

// 64B-row swizzle: XOR row bits into byte bits [5:4]
#define SWZ64(o) ((o) ^ (((o) >> 3) & 0x30))

#define CP16(dst, src) \
    asm volatile("cp.async.cg.shared.global [%0], [%1], 16;" :: "r"(dst), "l"(src) : "memory")
#define CP_COMMIT() asm volatile("cp.async.commit_group;" ::: "memory")
#define CP_WAIT1()  asm volatile("cp.async.wait_group 1;" ::: "memory")

#define LDMATRIX_X4(r0, r1, r2, r3, addr) \
    asm volatile("ldmatrix.sync.aligned.m8n8.x4.shared.b16 {%0,%1,%2,%3}, [%4];" \
                 : "=r"(r0), "=r"(r1), "=r"(r2), "=r"(r3) : "r"(addr))

#define MMA_BF16(c0, c1, c2, c3, a0, a1, a2, a3, b0, b1) \
    asm volatile("mma.sync.aligned.m16n8k16.row.col.f32.bf16.bf16.f32 " \
                 "{%0,%1,%2,%3}, {%4,%5,%6,%7}, {%8,%9}, {%0,%1,%2,%3};" \
                 : "+f"(c0), "+f"(c1), "+f"(c2), "+f"(c3) \
                 : "r"(a0), "r"(a1), "r"(a2), "r"(a3), "r"(b0), "r"(b1))

// term -> (A element offset, B element offset) within a KPAD row.
// term 0: ah*bh, term 1: al*bh, term 2: ah*bl
__device__ __forceinline__ void step_offsets(int i, int& ao, int& bo) {
    int term = i / NKT;
    int kt   = i - term * NKT;
    int ka   = (term == 1) ? SEG : 0;
    int kb   = (term == 2) ? SEG : 0;
    ao = ka + kt * BKT;
    bo = kb + kt * BKT;
}

// ---------------------------------------------------------------------------
// Kernel 1: fp32 -> bf16 hi/lo split + fused row-dot bias term.
// Output row layout: [hi(400) | 0(16) | lo(400) | 0(16)]  (KPAD=832)
// One warp per row. ws (optional) folds w3 in.
// ---------------------------------------------------------------------------
__global__ void convert_kernel(const float* __restrict__ x,
                               const float* __restrict__ wd,
                               const float* __restrict__ ws,   // may be null
                               __nv_bfloat16* __restrict__ xc,
                               float* __restrict__ rowdot,
                               int nrows)
{
    int warp = blockIdx.x * (blockDim.x >> 5) + (threadIdx.x >> 5);
    if (warp >= nrows) return;
    int lane = threadIdx.x & 31;

    const float4* xr  = reinterpret_cast<const float4*>(x + (size_t)warp * DDIM);
    const float4* wd4 = reinterpret_cast<const float4*>(wd);
    const float4* ws4 = ws ? reinterpret_cast<const float4*>(ws) : nullptr;
    __nv_bfloat16* rowc = xc + (size_t)warp * KPAD;

    float s = 0.f;
    for (int idx = lane; idx < DDIM / 4; idx += 32) {
        float4 v = xr[idx];
        float4 d = wd4[idx];
        s += v.x * d.x + v.y * d.y + v.z * d.z + v.w * d.w;
        float4 u = v;
        if (ws4) {
            float4 w = ws4[idx];
            u.x *= w.x; u.y *= w.y; u.z *= w.z; u.w *= w.w;
        }
        __nv_bfloat16 h0 = __float2bfloat16(u.x);
        __nv_bfloat16 h1 = __float2bfloat16(u.y);
        __nv_bfloat16 h2 = __float2bfloat16(u.z);
        __nv_bfloat16 h3 = __float2bfloat16(u.w);
        __nv_bfloat16 l0 = __float2bfloat16(u.x - __bfloat162float(h0));
        __nv_bfloat16 l1 = __float2bfloat16(u.y - __bfloat162float(h1));
        __nv_bfloat16 l2 = __float2bfloat16(u.z - __bfloat162float(h2));
        __nv_bfloat16 l3 = __float2bfloat16(u.w - __bfloat162float(h3));
        uint2 hp, lp;
        hp.x = ((uint32_t)__bfloat16_as_ushort(h1) << 16) | __bfloat16_as_ushort(h0);
        hp.y = ((uint32_t)__bfloat16_as_ushort(h3) << 16) | __bfloat16_as_ushort(h2);
        lp.x = ((uint32_t)__bfloat16_as_ushort(l1) << 16) | __bfloat16_as_ushort(l0);
        lp.y = ((uint32_t)__bfloat16_as_ushort(l3) << 16) | __bfloat16_as_ushort(l2);
        *reinterpret_cast<uint2*>(rowc + idx * 4)       = hp;
        *reinterpret_cast<uint2*>(rowc + SEG + idx * 4) = lp;
    }
    // zero pads: [400,416) and [816,832)
    rowc[(lane < 16) ? (DDIM + lane) : (DDIM + SEG - 16 + lane)] = __float2bfloat16(0.f);

    #pragma unroll
    for (int o = 16; o > 0; o >>= 1) s += __shfl_xor_sync(0xffffffffu, s, o);
    if (lane == 0) rowdot[warp] = s;
}

// ---------------------------------------------------------------------------
// Kernel 2: HMMA bf16 GEMM (3-term hi/lo, eff. K=1248) + fused bias epilogue.
// CTA 256x128, BK=32, 512 threads (16 warps, each 64x32), cp.async dbl-buffer.
// ---------------------------------------------------------------------------
#define A_ST   (BM * 64)          // 16384 B per stage (256 rows x 64B)
#define B_ST   (BN * 64)          //  8192 B
#define STG    (A_ST + B_ST)      // 24576
#define SMEM_REQ (1024 + 2 * STG) // 50176

__device__ __forceinline__ void load_tile(uint32_t stage, int s, int tid,
                                          const __nv_bfloat16* __restrict__ Abase,
                                          const __nv_bfloat16* __restrict__ Bbase,
                                          int ao, int bo)
{
    const uint32_t stgA = stage + s * STG;
    const uint32_t stgB = stgA + A_ST;
    // A: 256 rows x 4 chunks of 16B (2 per thread)
    #pragma unroll
    for (int it = 0; it < 2; it++) {
        int c = tid + it * 512;
        int row = c >> 2, cc = c & 3;
        uint32_t off = row * 64 + cc * 16;
        CP16(stgA + SWZ64(off), Abase + (size_t)row * KPAD + ao + cc * 8);
    }
    // B: 128 rows x 4 chunks (1 per thread)
    {
        int row = tid >> 2, cc = tid & 3;
        uint32_t off = row * 64 + cc * 16;
        CP16(stgB + SWZ64(off), Bbase + (size_t)row * KPAD + bo + cc * 8);
    }
}

__global__ void __launch_bounds__(512)
gemm_kernel(const __nv_bfloat16* __restrict__ Ac,
            const __nv_bfloat16* __restrict__ Bc,
            const float* __restrict__ ctxw1,
            const float* __restrict__ aspw2,
            float* __restrict__ out)
{
    extern __shared__ char smem[];
    const uint32_t stage = (smem_to_u32(smem) + 1023u) & ~1023u;

    const int tid  = threadIdx.x;
    const int wid  = tid >> 5, lane = tid & 31;
    const int wm   = wid & 3;          // 4 warps along M (64 rows each)
    const int wn   = wid >> 2;         // 4 warps along N (32 cols each)
    const int b    = blockIdx.z;
    const int m0   = blockIdx.y * BM;
    const int n0   = blockIdx.x * BN;

    const __nv_bfloat16* Abase = Ac + (size_t)(b * LC + m0) * KPAD;
    const __nv_bfloat16* Bbase = Bc + (size_t)(b * LA + n0) * KPAD;

    int ao, bo;
    step_offsets(0, ao, bo); load_tile(stage, 0, tid, Abase, Bbase, ao, bo); CP_COMMIT();
    step_offsets(1, ao, bo); load_tile(stage, 1, tid, Abase, Bbase, ao, bo); CP_COMMIT();

    float acc[4][4][4];
    #pragma unroll
    for (int mi = 0; mi < 4; mi++)
        #pragma unroll
        for (int ni = 0; ni < 4; ni++)
            #pragma unroll
            for (int q = 0; q < 4; q++) acc[mi][ni][q] = 0.f;

    // ldmatrix lane addressing (tile-relative byte offsets, before swizzle)
    const int aRow = wm * 64 + (lane & 15);
    const int aKb  = (lane >> 4) * 16;
    const int bRow = wn * 32 + ((lane >> 4) << 3) + (lane & 7);
    const int bKb  = ((lane >> 3) & 1) * 16;

    for (int i = 0; i < NSTEP; i++) {
        CP_WAIT1();
        __syncthreads();

        const uint32_t stgA = stage + (i & 1) * STG;
        const uint32_t stgB = stgA + A_ST;

        #pragma unroll
        for (int ks = 0; ks < 2; ks++) {
            uint32_t af[4][4];
            uint32_t bfr[2][4];
            #pragma unroll
            for (int mi = 0; mi < 4; mi++) {
                uint32_t off = (uint32_t)(aRow + mi * 16) * 64 + ks * 32 + aKb;
                LDMATRIX_X4(af[mi][0], af[mi][1], af[mi][2], af[mi][3],
                            stgA + SWZ64(off));
            }
            #pragma unroll
            for (int nj = 0; nj < 2; nj++) {
                uint32_t off = (uint32_t)(bRow + nj * 16) * 64 + ks * 32 + bKb;
                LDMATRIX_X4(bfr[nj][0], bfr[nj][1], bfr[nj][2], bfr[nj][3],
                            stgB + SWZ64(off));
            }
            #pragma unroll
            for (int mi = 0; mi < 4; mi++)
                #pragma unroll
                for (int ni = 0; ni < 4; ni++) {
                    uint32_t b0 = bfr[ni >> 1][(ni & 1) * 2 + 0];
                    uint32_t b1 = bfr[ni >> 1][(ni & 1) * 2 + 1];
                    MMA_BF16(acc[mi][ni][0], acc[mi][ni][1],
                             acc[mi][ni][2], acc[mi][ni][3],
                             af[mi][0], af[mi][1], af[mi][2], af[mi][3],
                             b0, b1);
                }
        }

        __syncthreads();   // everyone done reading stage (i&1) before refill
        if (i + 2 < NSTEP) {
            step_offsets(i + 2, ao, bo);
            load_tile(stage, i & 1, tid, Abase, Bbase, ao, bo);
        }
        CP_COMMIT();
    }

    // ---- epilogue: acc + ctxw1[row] + aspw2[col], float2 stores ----
    const int colq = 2 * (lane & 3);            // 0,2,4,6
    #pragma unroll
    for (int mi = 0; mi < 4; mi++) {
        int r0 = m0 + wm * 64 + mi * 16 + (lane >> 2);
        float cw0 = ctxw1[b * LC + r0];
        float cw8 = ctxw1[b * LC + r0 + 8];
        float* o0 = out + (size_t)(b * LC + r0) * LA + n0;
        float* o8 = o0 + 8 * LA;
        #pragma unroll
        for (int ni = 0; ni < 4; ni++) {
            int col = wn * 32 + ni * 8 + colq;
            float2 aw = *reinterpret_cast<const float2*>(aspw2 + b * LA + n0 + col);
            float2 v0, v8;
            v0.x = acc[mi][ni][0] + cw0 + aw.x;
            v0.y = acc[mi][ni][1] + cw0 + aw.y;
            v8.x = acc[mi][ni][2] + cw8 + aw.x;
            v8.y = acc[mi][ni][3] + cw8 + aw.y;
            *reinterpret_cast<float2*>(o0 + col) = v0;
            *reinterpret_cast<float2*>(o8 + col) = v8;
        }
    }
}

// ---------------------------------------------------------------------------
extern "C" void kernel_launch(void* const* d_in, const int* in_sizes, int n_in,
                              void* d_out, int out_size)
{
    const float* ctx = nullptr;
    const float* asp = nullptr;
    const float* wu  = nullptr;
    for (int i = 0; i < n_in; i++) {
        if (in_sizes[i] == BATCH * LC * DDIM)      ctx = (const float*)d_in[i];
        else if (in_sizes[i] == BATCH * LA * DDIM) asp = (const float*)d_in[i];
        else if (in_sizes[i] == 3 * DDIM)          wu  = (const float*)d_in[i];
    }
    float* out = (float*)d_out;

    __nv_bfloat16 *ctxc, *aspc;
    float *ctxw1p, *aspw2p;
    cudaGetSymbolAddress((void**)&ctxc,   g_ctx_c);
    cudaGetSymbolAddress((void**)&aspc,   g_asp_c);
    cudaGetSymbolAddress((void**)&ctxw1p, g_ctxw1);
    cudaGetSymbolAddress((void**)&aspw2p, g_aspw2);

    const float* w1 = wu;
    const float* w2 = wu + DDIM;
    const float* w3 = wu + 2 * DDIM;

    // split + fused rowdots (8 rows per 256-thread block)
    convert_kernel<<<(BATCH * LC) / 8, 256>>>(ctx, w1, w3, ctxc, ctxw1p, BATCH * LC);
    convert_kernel<<<(BATCH * LA) / 8, 256>>>(asp, w2, nullptr, aspc, aspw2p, BATCH * LA);

    // HMMA GEMM: grid (n-tiles, m-tiles, batch).
    // Unconditional (idempotent, host-side, capture-safe) — no static guards.
    cudaFuncSetAttribute(gemm_kernel,
                         cudaFuncAttributeMaxDynamicSharedMemorySize, SMEM_REQ);
    dim3 grid(LA / BN, LC / BM, BATCH);   // (4, 8, 64)
    gemm_kernel<<<grid, 512, SMEM_REQ>>>(ctxc, aspc, ctxw1p, aspw2p, out);
}

// round 14
// speedup vs baseline: 2.6457x; 1.2580x over previous
#include <cuda_runtime.h>
#include <cuda_bf16.h>
#include <cstdint>

// ---------------------------------------------------------------------------
// Problem constants
// ---------------------------------------------------------------------------
#define BATCH 64
#define LC    2048
#define LA    512
#define DDIM  400
#define SEG   416           // padded segment (400 data + 16 zeros)
#define KPAD  832           // [hi(400) pad16 | lo(400) pad16]
#define NKT   13            // 416 / 32 k-tiles per term
#define NSTEP 39            // 3 terms x 13 k-tiles

// GEMM tile
#define BM 128
#define BN 128
#define BKT 32
#define NSTAGE 4

// ---------------------------------------------------------------------------
// Device scratch (no cudaMalloc allowed)
// ---------------------------------------------------------------------------
__device__ __align__(256) __nv_bfloat16 g_ctx_c[(size_t)BATCH * LC * KPAD]; // 218 MB
__device__ __align__(256) __nv_bfloat16 g_asp_c[(size_t)BATCH * LA * KPAD]; //  54 MB
__device__ float g_ctxw1[BATCH * LC];
__device__ float g_aspw2[BATCH * LA];

// ---------------------------------------------------------------------------
// Helpers
// ---------------------------------------------------------------------------
__device__ __forceinline__ uint32_t smem_to_u32(const void* p) {
    uint32_t a;
    asm("{ .reg .u64 t; cvta.to.shared.u64 t, %1; cvt.u32.u64 %0, t; }" : "=r"(a) : "l"(p));
    return a;
}

// 64B-row swizzle: XOR row bits into byte bits [5:4]
#define SWZ64(o) ((o) ^ (((o) >> 3) & 0x30))

#define CP16(dst, src) \
    asm volatile("cp.async.cg.shared.global [%0], [%1], 16;" :: "r"(dst), "l"(src) : "memory")
#define CP_COMMIT() asm volatile("cp.async.commit_group;" ::: "memory")
#define CP_WAITG2() asm volatile("cp.async.wait_group 2;" ::: "memory")

#define LDMATRIX_X4(r0, r1, r2, r3, addr) \
    asm volatile("ldmatrix.sync.aligned.m8n8.x4.shared.b16 {%0,%1,%2,%3}, [%4];" \
                 : "=r"(r0), "=r"(r1), "=r"(r2), "=r"(r3) : "r"(addr))

#define MMA_BF16(c0, c1, c2, c3, a0, a1, a2, a3, b0, b1) \
    asm volatile("mma.sync.aligned.m16n8k16.row.col.f32.bf16.bf16.f32 " \
                 "{%0,%1,%2,%3}, {%4,%5,%6,%7}, {%8,%9}, {%0,%1,%2,%3};" \
                 : "+f"(c0), "+f"(c1), "+f"(c2), "+f"(c3) \
                 : "r"(a0), "r"(a1), "r"(a2), "r"(a3), "r"(b0), "r"(b1))

// term -> (A element offset, B element offset) within a KPAD row.
// term 0: ah*bh, term 1: al*bh, term 2: ah*bl
__device__ __forceinline__ void step_offsets(int i, int& ao, int& bo) {
    int term = i / NKT;
    int kt   = i - term * NKT;
    int ka   = (term == 1) ? SEG : 0;
    int kb   = (term == 2) ? SEG : 0;
    ao = ka + kt * BKT;
    bo = kb + kt * BKT;
}

// ---------------------------------------------------------------------------
// Kernel 1: fp32 -> bf16 hi/lo split + fused row-dot bias term.
// Output row layout: [hi(400) | 0(16) | lo(400) | 0(16)]  (KPAD=832)
// One warp per row. ws (optional) folds w3 in.
// ---------------------------------------------------------------------------
__global__ void convert_kernel(const float* __restrict__ x,
                               const float* __restrict__ wd,
                               const float* __restrict__ ws,   // may be null
                               __nv_bfloat16* __restrict__ xc,
                               float* __restrict__ rowdot,
                               int nrows)
{
    int warp = blockIdx.x * (blockDim.x >> 5) + (threadIdx.x >> 5);
    if (warp >= nrows) return;
    int lane = threadIdx.x & 31;

    const float4* xr  = reinterpret_cast<const float4*>(x + (size_t)warp * DDIM);
    const float4* wd4 = reinterpret_cast<const float4*>(wd);
    const float4* ws4 = ws ? reinterpret_cast<const float4*>(ws) : nullptr;
    __nv_bfloat16* rowc = xc + (size_t)warp * KPAD;

    float s = 0.f;
    for (int idx = lane; idx < DDIM / 4; idx += 32) {
        float4 v = xr[idx];
        float4 d = wd4[idx];
        s += v.x * d.x + v.y * d.y + v.z * d.z + v.w * d.w;
        float4 u = v;
        if (ws4) {
            float4 w = ws4[idx];
            u.x *= w.x; u.y *= w.y; u.z *= w.z; u.w *= w.w;
        }
        __nv_bfloat16 h0 = __float2bfloat16(u.x);
        __nv_bfloat16 h1 = __float2bfloat16(u.y);
        __nv_bfloat16 h2 = __float2bfloat16(u.z);
        __nv_bfloat16 h3 = __float2bfloat16(u.w);
        __nv_bfloat16 l0 = __float2bfloat16(u.x - __bfloat162float(h0));
        __nv_bfloat16 l1 = __float2bfloat16(u.y - __bfloat162float(h1));
        __nv_bfloat16 l2 = __float2bfloat16(u.z - __bfloat162float(h2));
        __nv_bfloat16 l3 = __float2bfloat16(u.w - __bfloat162float(h3));
        uint2 hp, lp;
        hp.x = ((uint32_t)__bfloat16_as_ushort(h1) << 16) | __bfloat16_as_ushort(h0);
        hp.y = ((uint32_t)__bfloat16_as_ushort(h3) << 16) | __bfloat16_as_ushort(h2);
        lp.x = ((uint32_t)__bfloat16_as_ushort(l1) << 16) | __bfloat16_as_ushort(l0);
        lp.y = ((uint32_t)__bfloat16_as_ushort(l3) << 16) | __bfloat16_as_ushort(l2);
        *reinterpret_cast<uint2*>(rowc + idx * 4)       = hp;
        *reinterpret_cast<uint2*>(rowc + SEG + idx * 4) = lp;
    }
    // zero pads: [400,416) and [816,832)
    rowc[(lane < 16) ? (DDIM + lane) : (DDIM + SEG - 16 + lane)] = __float2bfloat16(0.f);

    #pragma unroll
    for (int o = 16; o > 0; o >>= 1) s += __shfl_xor_sync(0xffffffffu, s, o);
    if (lane == 0) rowdot[warp] = s;
}

// ---------------------------------------------------------------------------
// Kernel 2: HMMA bf16 GEMM (3-term hi/lo, eff. K=1248) + fused bias epilogue.
// CTA 128x128, 256 threads (8 warps, each 64x32), 4-stage cp.async ring,
// ONE __syncthreads per k-step, 2 CTAs/SM.
// ---------------------------------------------------------------------------
#define A_ST   (BM * 64)              // 8192 B per stage
#define B_ST   (BN * 64)              // 8192 B
#define STG    (A_ST + B_ST)          // 16384
#define SMEM_REQ (1024 + NSTAGE * STG) // 66560

__device__ __forceinline__ void load_tile(uint32_t stage, int s, int tid,
                                          const __nv_bfloat16* __restrict__ Abase,
                                          const __nv_bfloat16* __restrict__ Bbase,
                                          int ao, int bo)
{
    const uint32_t stgA = stage + s * STG;
    const uint32_t stgB = stgA + A_ST;
    // A: 128 rows x 4 chunks of 16B (2 per thread)
    #pragma unroll
    for (int it = 0; it < 2; it++) {
        int c = tid + it * 256;
        int row = c >> 2, cc = c & 3;
        uint32_t off = row * 64 + cc * 16;
        CP16(stgA + SWZ64(off), Abase + (size_t)row * KPAD + ao + cc * 8);
    }
    // B: 128 rows x 4 chunks (2 per thread)
    #pragma unroll
    for (int it = 0; it < 2; it++) {
        int c = tid + it * 256;
        int row = c >> 2, cc = c & 3;
        uint32_t off = row * 64 + cc * 16;
        CP16(stgB + SWZ64(off), Bbase + (size_t)row * KPAD + bo + cc * 8);
    }
}

__global__ void __launch_bounds__(256, 2)
gemm_kernel(const __nv_bfloat16* __restrict__ Ac,
            const __nv_bfloat16* __restrict__ Bc,
            const float* __restrict__ ctxw1,
            const float* __restrict__ aspw2,
            float* __restrict__ out)
{
    extern __shared__ char smem[];
    const uint32_t stage = (smem_to_u32(smem) + 1023u) & ~1023u;

    const int tid  = threadIdx.x;
    const int wid  = tid >> 5, lane = tid & 31;
    const int wm   = wid & 1;          // 2 warps along M (64 rows each)
    const int wn   = wid >> 1;         // 4 warps along N (32 cols each)
    const int b    = blockIdx.z;
    const int m0   = blockIdx.y * BM;
    const int n0   = blockIdx.x * BN;

    const __nv_bfloat16* Abase = Ac + (size_t)(b * LC + m0) * KPAD;
    const __nv_bfloat16* Bbase = Bc + (size_t)(b * LA + n0) * KPAD;

    int ao, bo;
    step_offsets(0, ao, bo); load_tile(stage, 0, tid, Abase, Bbase, ao, bo); CP_COMMIT();
    step_offsets(1, ao, bo); load_tile(stage, 1, tid, Abase, Bbase, ao, bo); CP_COMMIT();
    step_offsets(2, ao, bo); load_tile(stage, 2, tid, Abase, Bbase, ao, bo); CP_COMMIT();

    float acc[4][4][4];
    #pragma unroll
    for (int mi = 0; mi < 4; mi++)
        #pragma unroll
        for (int ni = 0; ni < 4; ni++)
            #pragma unroll
            for (int q = 0; q < 4; q++) acc[mi][ni][q] = 0.f;

    // ldmatrix lane addressing (tile-relative byte offsets, before swizzle)
    const int aRow = wm * 64 + (lane & 15);
    const int aKb  = (lane >> 4) * 16;
    const int bRow = wn * 32 + ((lane >> 4) << 3) + (lane & 7);
    const int bKb  = ((lane >> 3) & 1) * 16;

    for (int i = 0; i < NSTEP; i++) {
        CP_WAITG2();               // stage i resident (<=2 younger groups pending)
        __syncthreads();

        const uint32_t stgA = stage + (i & 3) * STG;
        const uint32_t stgB = stgA + A_ST;

        #pragma unroll
        for (int ks = 0; ks < 2; ks++) {
            uint32_t af[4][4];
            uint32_t bfr[2][4];
            #pragma unroll
            for (int mi = 0; mi < 4; mi++) {
                uint32_t off = (uint32_t)(aRow + mi * 16) * 64 + ks * 32 + aKb;
                LDMATRIX_X4(af[mi][0], af[mi][1], af[mi][2], af[mi][3],
                            stgA + SWZ64(off));
            }
            #pragma unroll
            for (int nj = 0; nj < 2; nj++) {
                uint32_t off = (uint32_t)(bRow + nj * 16) * 64 + ks * 32 + bKb;
                LDMATRIX_X4(bfr[nj][0], bfr[nj][1], bfr[nj][2], bfr[nj][3],
                            stgB + SWZ64(off));
            }
            #pragma unroll
            for (int mi = 0; mi < 4; mi++)
                #pragma unroll
                for (int ni = 0; ni < 4; ni++) {
                    uint32_t b0 = bfr[ni >> 1][(ni & 1) * 2 + 0];
                    uint32_t b1 = bfr[ni >> 1][(ni & 1) * 2 + 1];
                    MMA_BF16(acc[mi][ni][0], acc[mi][ni][1],
                             acc[mi][ni][2], acc[mi][ni][3],
                             af[mi][0], af[mi][1], af[mi][2], af[mi][3],
                             b0, b1);
                }
        }

        // Prefetch stage i+3 into ring slot (i+3)&3 == (i-1)&3.
        // Safe with ONE sync: that slot was consumed at iter i-1, and every
        // warp passed this iter's __syncthreads after finishing it.
        if (i + 3 < NSTEP) {
            step_offsets(i + 3, ao, bo);
            load_tile(stage, (i + 3) & 3, tid, Abase, Bbase, ao, bo);
        }
        CP_COMMIT();
    }

    // ---- epilogue: acc + ctxw1[row] + aspw2[col], float2 stores ----
    const int colq = 2 * (lane & 3);            // 0,2,4,6
    #pragma unroll
    for (int mi = 0; mi < 4; mi++) {
        int r0 = m0 + wm * 64 + mi * 16 + (lane >> 2);
        float cw0 = ctxw1[b * LC + r0];
        float cw8 = ctxw1[b * LC + r0 + 8];
        float* o0 = out + (size_t)(b * LC + r0) * LA + n0;
        float* o8 = o0 + 8 * LA;
        #pragma unroll
        for (int ni = 0; ni < 4; ni++) {
            int col = wn * 32 + ni * 8 + colq;
            float2 aw = *reinterpret_cast<const float2*>(aspw2 + b * LA + n0 + col);
            float2 v0, v8;
            v0.x = acc[mi][ni][0] + cw0 + aw.x;
            v0.y = acc[mi][ni][1] + cw0 + aw.y;
            v8.x = acc[mi][ni][2] + cw8 + aw.x;
            v8.y = acc[mi][ni][3] + cw8 + aw.y;
            *reinterpret_cast<float2*>(o0 + col) = v0;
            *reinterpret_cast<float2*>(o8 + col) = v8;
        }
    }
}

// ---------------------------------------------------------------------------
extern "C" void kernel_launch(void* const* d_in, const int* in_sizes, int n_in,
                              void* d_out, int out_size)
{
    const float* ctx = nullptr;
    const float* asp = nullptr;
    const float* wu  = nullptr;
    for (int i = 0; i < n_in; i++) {
        if (in_sizes[i] == BATCH * LC * DDIM)      ctx = (const float*)d_in[i];
        else if (in_sizes[i] == BATCH * LA * DDIM) asp = (const float*)d_in[i];
        else if (in_sizes[i] == 3 * DDIM)          wu  = (const float*)d_in[i];
    }
    float* out = (float*)d_out;

    __nv_bfloat16 *ctxc, *aspc;
    float *ctxw1p, *aspw2p;
    cudaGetSymbolAddress((void**)&ctxc,   g_ctx_c);
    cudaGetSymbolAddress((void**)&aspc,   g_asp_c);
    cudaGetSymbolAddress((void**)&ctxw1p, g_ctxw1);
    cudaGetSymbolAddress((void**)&aspw2p, g_aspw2);

    const float* w1 = wu;
    const float* w2 = wu + DDIM;
    const float* w3 = wu + 2 * DDIM;

    // split + fused rowdots (8 rows per 256-thread block)
    convert_kernel<<<(BATCH * LC) / 8, 256>>>(ctx, w1, w3, ctxc, ctxw1p, BATCH * LC);
    convert_kernel<<<(BATCH * LA) / 8, 256>>>(asp, w2, nullptr, aspc, aspw2p, BATCH * LA);

    // HMMA GEMM: grid (n-tiles, m-tiles, batch).
    cudaFuncSetAttribute(gemm_kernel,
                         cudaFuncAttributeMaxDynamicSharedMemorySize, SMEM_REQ);
    dim3 grid(LA / BN, LC / BM, BATCH);   // (4, 16, 64)
    gemm_kernel<<<grid, 256, SMEM_REQ>>>(ctxc, aspc, ctxw1p, aspw2p, out);
}